// round 1
// baseline (speedup 1.0000x reference)
#include <cuda_runtime.h>
#include <cstdint>
#include <cstddef>

#define NTOK 2048
#define DIN  1024
#define DHID 4096
#define DOUT 1024
#define NEXP 8
#define CAP  2048   // per-expert row capacity (worst case: every token picks e)

// ---------------- scratch (static device globals; no allocs allowed) ----------------
__device__ int   g_cnt[NEXP];
__device__ int   g_tok_of_row[NEXP * CAP];
__device__ int   g_slot_row[NTOK * 2];
__device__ float g_slot_w[NTOK * 2];
__device__ float g_H[(size_t)NEXP * CAP * DHID];  // 256 MB
__device__ float g_Y[(size_t)NEXP * CAP * DOUT];  // 64 MB

// ---------------- helpers ----------------
__device__ __forceinline__ uint32_t f2tf(float f) {
    uint32_t r;
    asm("cvt.rna.tf32.f32 %0, %1;" : "=r"(r) : "f"(f));
    return r;
}

__device__ __forceinline__ void cp16(uint32_t saddr, const void* gaddr) {
    asm volatile("cp.async.cg.shared.global [%0], [%1], 16;" :: "r"(saddr), "l"(gaddr));
}

__device__ __forceinline__ void mma8(float c[4], const uint32_t a[4], const uint32_t b[2]) {
    asm volatile(
        "mma.sync.aligned.m16n8k8.row.col.f32.tf32.tf32.f32 "
        "{%0,%1,%2,%3},{%4,%5,%6,%7},{%8,%9},{%0,%1,%2,%3};"
        : "+f"(c[0]), "+f"(c[1]), "+f"(c[2]), "+f"(c[3])
        : "r"(a[0]), "r"(a[1]), "r"(a[2]), "r"(a[3]), "r"(b[0]), "r"(b[1]));
}

// ---------------- kernel 0: zero counters ----------------
__global__ void init_kernel() {
    if (threadIdx.x < NEXP) g_cnt[threadIdx.x] = 0;
}

// ---------------- kernel 1: gate + routing ----------------
// 256 threads = 8 warps, one token per warp. gate_w cached in smem.
__global__ void gate_kernel(const float* __restrict__ x,
                            const float* __restrict__ gw,
                            const float* __restrict__ gb) {
    __shared__ float sgw[NEXP * DIN];  // 32 KB
    const int t = threadIdx.x;
    for (int i = t; i < NEXP * DIN / 4; i += 256)
        ((float4*)sgw)[i] = ((const float4*)gw)[i];
    __syncthreads();

    const int warp = t >> 5, lane = t & 31;
    const int n = blockIdx.x * 8 + warp;

    float acc[NEXP];
#pragma unroll
    for (int e = 0; e < NEXP; e++) acc[e] = 0.f;

    const float* xr = x + (size_t)n * DIN;
    for (int kk = 0; kk < DIN; kk += 32) {
        float xv = xr[kk + lane];
#pragma unroll
        for (int e = 0; e < NEXP; e++)
            acc[e] = fmaf(xv, sgw[e * DIN + kk + lane], acc[e]);
    }
#pragma unroll
    for (int off = 16; off; off >>= 1) {
#pragma unroll
        for (int e = 0; e < NEXP; e++)
            acc[e] += __shfl_xor_sync(0xffffffffu, acc[e], off);
    }

    if (lane == 0) {
        float lg[NEXP];
#pragma unroll
        for (int e = 0; e < NEXP; e++) lg[e] = acc[e] + gb[e];
        // top-2, lowest index wins ties (matches jax.lax.top_k)
        int e0 = 0;
#pragma unroll
        for (int e = 1; e < NEXP; e++) if (lg[e] > lg[e0]) e0 = e;
        int e1 = (e0 == 0) ? 1 : 0;
#pragma unroll
        for (int e = 0; e < NEXP; e++) if (e != e0 && lg[e] > lg[e1]) e1 = e;

        float z  = expf(lg[e1] - lg[e0]);   // <= 1, stable
        float w0 = 1.f / (1.f + z);
        float w1 = z / (1.f + z);

        int s0 = atomicAdd(&g_cnt[e0], 1);
        int s1 = atomicAdd(&g_cnt[e1], 1);
        int r0 = e0 * CAP + s0;
        int r1 = e1 * CAP + s1;
        g_tok_of_row[r0] = n;
        g_tok_of_row[r1] = n;
        g_slot_row[2 * n]     = r0;
        g_slot_row[2 * n + 1] = r1;
        g_slot_w[2 * n]     = w0;
        g_slot_w[2 * n + 1] = w1;
    }
}

// ---------------- kernels 2/3: expert GEMMs (tf32 mma.sync) ----------------
// MODE 1: H[e-rows] = relu( gather(x) @ W1[e]^T + b1[e] )   (K=1024, N=4096)
// MODE 2: Y[e-rows] =        H        @ W2[e]^T + b2[e]     (K=4096, N=1024)
// Block tile 128x128xBK32, 256 threads (2x4 warps, 64x32 warp tile),
// cp.async double-buffered, smem row pitch 36 floats (conflict-free frag loads).
#define SM_PITCH 36
#define SM_BUF   (128 * SM_PITCH)           // 4608 floats per buffer
#define SMEM_FLOATS (4 * SM_BUF)            // A0,A1,B0,B1
#define SMEM_BYTES  (SMEM_FLOATS * 4)       // 73728

template <int MODE>
__global__ void __launch_bounds__(256, 2) moe_gemm(const float* __restrict__ Ain,
                                                   const float* __restrict__ Wt,
                                                   const float* __restrict__ bias) {
    constexpr int KD = (MODE == 1) ? DIN : DHID;
    constexpr int ND = (MODE == 1) ? DHID : DOUT;
    constexpr int KT = KD / 32;

    const int e  = blockIdx.z;
    const int m0 = blockIdx.y * 128;
    const int n0 = blockIdx.x * 128;
    const int cnt = g_cnt[e];
    if (m0 >= cnt) return;

    extern __shared__ float sm[];
    const int t = threadIdx.x;
    const int lane = t & 31, warp = t >> 5;
    const int wm = warp >> 2, wn = warp & 3;         // 2 x 4 warp grid
    const int grp = lane >> 2, tig = lane & 3;

    const float* gA[4];
    const float* gB[4];
    uint32_t sA[4], sB[4];
    const uint32_t smbase = (uint32_t)__cvta_generic_to_shared(sm);

#pragma unroll
    for (int j = 0; j < 4; j++) {
        int i = t + 256 * j;          // float4 index in 128x32 tile
        int row = i >> 3;             // 0..127
        int col = (i & 7) * 4;        // 0..28
        if (MODE == 1) {
            int r = m0 + row;
            int tok = (r < cnt) ? g_tok_of_row[e * CAP + r] : g_tok_of_row[e * CAP];
            gA[j] = Ain + (size_t)tok * KD + col;
        } else {
            gA[j] = g_H + (size_t)(e * CAP + m0 + row) * KD + col;
        }
        gB[j] = Wt + ((size_t)e * ND + n0 + row) * KD + col;
        sA[j] = smbase + (uint32_t)(row * SM_PITCH + col) * 4u;
        sB[j] = smbase + (uint32_t)(2 * SM_BUF + row * SM_PITCH + col) * 4u;
    }

    float c[4][4][4];
#pragma unroll
    for (int am = 0; am < 4; am++)
#pragma unroll
        for (int bn = 0; bn < 4; bn++)
#pragma unroll
            for (int i = 0; i < 4; i++) c[am][bn][i] = 0.f;

    // prologue: tile 0 -> buffer 0
#pragma unroll
    for (int j = 0; j < 4; j++) cp16(sA[j], gA[j]);
#pragma unroll
    for (int j = 0; j < 4; j++) cp16(sB[j], gB[j]);
    asm volatile("cp.async.commit_group;");
    asm volatile("cp.async.wait_group 0;");
    __syncthreads();

    for (int kt = 0; kt < KT; kt++) {
        const int cur = kt & 1;
        if (kt + 1 < KT) {
            const uint32_t boff = (uint32_t)(((kt + 1) & 1) * SM_BUF) * 4u;
            const int kof = (kt + 1) * 32;
#pragma unroll
            for (int j = 0; j < 4; j++) cp16(sA[j] + boff, gA[j] + kof);
#pragma unroll
            for (int j = 0; j < 4; j++) cp16(sB[j] + boff, gB[j] + kof);
            asm volatile("cp.async.commit_group;");
        }

        const float* As = sm + cur * SM_BUF;
        const float* Bs = sm + 2 * SM_BUF + cur * SM_BUF;

#pragma unroll
        for (int ks = 0; ks < 4; ks++) {
            const int k0 = ks * 8;
            uint32_t a[4][4], b[4][2];
#pragma unroll
            for (int am = 0; am < 4; am++) {
                int base = (wm * 64 + am * 16 + grp) * SM_PITCH + k0 + tig;
                a[am][0] = f2tf(As[base]);
                a[am][1] = f2tf(As[base + 8 * SM_PITCH]);
                a[am][2] = f2tf(As[base + 4]);
                a[am][3] = f2tf(As[base + 8 * SM_PITCH + 4]);
            }
#pragma unroll
            for (int bn = 0; bn < 4; bn++) {
                int base = (wn * 32 + bn * 8 + grp) * SM_PITCH + k0 + tig;
                b[bn][0] = f2tf(Bs[base]);
                b[bn][1] = f2tf(Bs[base + 4]);
            }
#pragma unroll
            for (int am = 0; am < 4; am++)
#pragma unroll
                for (int bn = 0; bn < 4; bn++)
                    mma8(c[am][bn], a[am], b[bn]);
        }

        if (kt + 1 < KT) {
            asm volatile("cp.async.wait_group 0;");
            __syncthreads();
        }
    }

    // epilogue
    const float* bv = bias + (size_t)e * ND + n0;
    float* Dst = (MODE == 1) ? g_H : g_Y;
#pragma unroll
    for (int bn = 0; bn < 4; bn++) {
        const int cg = wn * 32 + bn * 8 + tig * 2;
        const float b0v = bv[cg], b1v = bv[cg + 1];
#pragma unroll
        for (int am = 0; am < 4; am++) {
            const int rl = wm * 64 + am * 16 + grp;
            float v0 = c[am][bn][0] + b0v;
            float v1 = c[am][bn][1] + b1v;
            float v2 = c[am][bn][2] + b0v;
            float v3 = c[am][bn][3] + b1v;
            if (MODE == 1) {
                v0 = fmaxf(v0, 0.f); v1 = fmaxf(v1, 0.f);
                v2 = fmaxf(v2, 0.f); v3 = fmaxf(v3, 0.f);
            }
            const size_t base0 = (size_t)(e * CAP + m0 + rl) * ND + n0 + cg;
            const size_t base1 = (size_t)(e * CAP + m0 + rl + 8) * ND + n0 + cg;
            *reinterpret_cast<float2*>(Dst + base0) = make_float2(v0, v1);
            *reinterpret_cast<float2*>(Dst + base1) = make_float2(v2, v3);
        }
    }
}

// ---------------- kernel 4: weighted combine ----------------
__global__ void combine_kernel(float* __restrict__ out) {
    const int n = blockIdx.x, t = threadIdx.x;
    const int r0 = g_slot_row[2 * n], r1 = g_slot_row[2 * n + 1];
    const float w0 = g_slot_w[2 * n], w1 = g_slot_w[2 * n + 1];
    const float4 a = reinterpret_cast<const float4*>(g_Y + (size_t)r0 * DOUT)[t];
    const float4 b = reinterpret_cast<const float4*>(g_Y + (size_t)r1 * DOUT)[t];
    float4 o;
    o.x = w0 * a.x + w1 * b.x;
    o.y = w0 * a.y + w1 * b.y;
    o.z = w0 * a.z + w1 * b.z;
    o.w = w0 * a.w + w1 * b.w;
    reinterpret_cast<float4*>(out + (size_t)n * DOUT)[t] = o;
}

// ---------------- launch ----------------
extern "C" void kernel_launch(void* const* d_in, const int* in_sizes, int n_in,
                              void* d_out, int out_size) {
    const float* x  = (const float*)d_in[0];
    const float* gw = (const float*)d_in[1];
    const float* gb = (const float*)d_in[2];
    const float* W1 = (const float*)d_in[3];
    const float* b1 = (const float*)d_in[4];
    const float* W2 = (const float*)d_in[5];
    const float* b2 = (const float*)d_in[6];
    float* out = (float*)d_out;

    cudaFuncSetAttribute(moe_gemm<1>, cudaFuncAttributeMaxDynamicSharedMemorySize, SMEM_BYTES);
    cudaFuncSetAttribute(moe_gemm<2>, cudaFuncAttributeMaxDynamicSharedMemorySize, SMEM_BYTES);

    init_kernel<<<1, 32>>>();
    gate_kernel<<<NTOK / 8, 256>>>(x, gw, gb);
    moe_gemm<1><<<dim3(DHID / 128, CAP / 128, NEXP), 256, SMEM_BYTES>>>(x,       W1, b1);
    moe_gemm<2><<<dim3(DOUT / 128, CAP / 128, NEXP), 256, SMEM_BYTES>>>(nullptr, W2, b2);
    combine_kernel<<<NTOK, 256>>>(out);
}

// round 4
// speedup vs baseline: 1.1294x; 1.1294x over previous
#include <cuda_runtime.h>
#include <cstdint>
#include <cstddef>

#define NTOK 2048
#define DIN  1024
#define DHID 4096
#define DOUT 1024
#define NEXP 8
#define CAP  2048

// ---------------- scratch (static device globals; no allocs allowed) ----------------
__device__ int   g_cnt[NEXP];
__device__ int   g_tok_of_row[NEXP * CAP];
__device__ int   g_slot_row[NTOK * 2];
__device__ float g_slot_w[NTOK * 2];
__device__ float g_X[(size_t)NTOK * DIN];         // tf32-rounded copy of x
__device__ float g_H[(size_t)NEXP * CAP * DHID];  // 256 MB (tf32-rounded)
__device__ float g_Y[(size_t)NEXP * CAP * DOUT];  // 64 MB

// ---------------- helpers ----------------
__device__ __forceinline__ uint32_t f2tf(float f) {
    uint32_t r;
    asm("cvt.rna.tf32.f32 %0, %1;" : "=r"(r) : "f"(f));
    return r;
}
__device__ __forceinline__ float rnd_tf32(float f) { return __uint_as_float(f2tf(f)); }

__device__ __forceinline__ void cp16(uint32_t saddr, const void* gaddr) {
    asm volatile("cp.async.cg.shared.global [%0], [%1], 16;" :: "r"(saddr), "l"(gaddr));
}

__device__ __forceinline__ void ldsm4(uint32_t r[4], uint32_t addr) {
    asm volatile("ldmatrix.sync.aligned.m8n8.x4.shared.b16 {%0,%1,%2,%3}, [%4];"
                 : "=r"(r[0]), "=r"(r[1]), "=r"(r[2]), "=r"(r[3]) : "r"(addr));
}
__device__ __forceinline__ void ldsm2(uint32_t r[2], uint32_t addr) {
    asm volatile("ldmatrix.sync.aligned.m8n8.x2.shared.b16 {%0,%1}, [%2];"
                 : "=r"(r[0]), "=r"(r[1]) : "r"(addr));
}

__device__ __forceinline__ void mma8(float c[4], const uint32_t a[4], const uint32_t b[2]) {
    asm volatile(
        "mma.sync.aligned.m16n8k8.row.col.f32.tf32.tf32.f32 "
        "{%0,%1,%2,%3},{%4,%5,%6,%7},{%8,%9},{%0,%1,%2,%3};"
        : "+f"(c[0]), "+f"(c[1]), "+f"(c[2]), "+f"(c[3])
        : "r"(a[0]), "r"(a[1]), "r"(a[2]), "r"(a[3]), "r"(b[0]), "r"(b[1]));
}

// ---------------- kernel 0: zero counters ----------------
__global__ void init_kernel() {
    if (threadIdx.x < NEXP) g_cnt[threadIdx.x] = 0;
}

// ---------------- kernel 0b: pre-round x to tf32 (A operand of GEMM1) ----------------
__global__ void round_x_kernel(const float* __restrict__ x) {
    const int i = blockIdx.x * 256 + threadIdx.x;       // float4 index
    float4 v = ((const float4*)x)[i];
    v.x = rnd_tf32(v.x); v.y = rnd_tf32(v.y);
    v.z = rnd_tf32(v.z); v.w = rnd_tf32(v.w);
    ((float4*)g_X)[i] = v;
}

// ---------------- kernel 1: gate + routing ----------------
__global__ void gate_kernel(const float* __restrict__ x,
                            const float* __restrict__ gw,
                            const float* __restrict__ gb) {
    __shared__ float sgw[NEXP * DIN];  // 32 KB
    const int t = threadIdx.x;
    for (int i = t; i < NEXP * DIN / 4; i += 256)
        ((float4*)sgw)[i] = ((const float4*)gw)[i];
    __syncthreads();

    const int warp = t >> 5, lane = t & 31;
    const int n = blockIdx.x * 8 + warp;

    float acc[NEXP];
#pragma unroll
    for (int e = 0; e < NEXP; e++) acc[e] = 0.f;

    const float* xr = x + (size_t)n * DIN;
    for (int kk = 0; kk < DIN; kk += 32) {
        float xv = xr[kk + lane];
#pragma unroll
        for (int e = 0; e < NEXP; e++)
            acc[e] = fmaf(xv, sgw[e * DIN + kk + lane], acc[e]);
    }
#pragma unroll
    for (int off = 16; off; off >>= 1) {
#pragma unroll
        for (int e = 0; e < NEXP; e++)
            acc[e] += __shfl_xor_sync(0xffffffffu, acc[e], off);
    }

    if (lane == 0) {
        float lg[NEXP];
#pragma unroll
        for (int e = 0; e < NEXP; e++) lg[e] = acc[e] + gb[e];
        int e0 = 0;
#pragma unroll
        for (int e = 1; e < NEXP; e++) if (lg[e] > lg[e0]) e0 = e;
        int e1 = (e0 == 0) ? 1 : 0;
#pragma unroll
        for (int e = 0; e < NEXP; e++) if (e != e0 && lg[e] > lg[e1]) e1 = e;

        float z  = expf(lg[e1] - lg[e0]);
        float w0 = 1.f / (1.f + z);
        float w1 = z / (1.f + z);

        int s0 = atomicAdd(&g_cnt[e0], 1);
        int s1 = atomicAdd(&g_cnt[e1], 1);
        int r0 = e0 * CAP + s0;
        int r1 = e1 * CAP + s1;
        g_tok_of_row[r0] = n;
        g_tok_of_row[r1] = n;
        g_slot_row[2 * n]     = r0;
        g_slot_row[2 * n + 1] = r1;
        g_slot_w[2 * n]     = w0;
        g_slot_w[2 * n + 1] = w1;
    }
}

// ---------------- kernels 2/3: expert GEMMs (tf32 mma.sync + ldmatrix) ----------------
// MODE 1: H = relu( gather(g_X) @ W1[e]^T + b1[e] ), rounded to tf32  (K=1024, N=4096)
// MODE 2: Y =            g_H     @ W2[e]^T + b2[e]                    (K=4096, N=1024)
// Block 128x128xBK32, 256 threads (2x4 warps, 64x32 warp tiles), 3-stage cp.async,
// ldmatrix fragment loads (A pre-rounded; only B needs cvt.rna.tf32).
#define SM_PITCH  36
#define STAGES    3
#define STAGE_FL  (128 * SM_PITCH)              // 4608 floats
#define STAGE_BYT (STAGE_FL * 4)                // 18432 bytes
#define SMEM_BYTES (STAGES * 2 * STAGE_BYT)     // 110592 bytes

template <int MODE>
__global__ void __launch_bounds__(256, 2) moe_gemm(const float* __restrict__ Wt,
                                                   const float* __restrict__ bias) {
    constexpr int KD = (MODE == 1) ? DIN : DHID;
    constexpr int ND = (MODE == 1) ? DHID : DOUT;
    constexpr int KT = KD / 32;

    const int e  = blockIdx.z;
    const int m0 = blockIdx.y * 128;
    const int n0 = blockIdx.x * 128;
    const int cnt = g_cnt[e];
    if (m0 >= cnt) return;

    extern __shared__ char smc[];
    const uint32_t smbase = (uint32_t)__cvta_generic_to_shared(smc);
    const int t = threadIdx.x;
    const int lane = t & 31, warp = t >> 5;
    const int wm = warp >> 2, wn = warp & 3;         // 2 x 4 warp grid

    // ---- producer pointers: 4 float4 chunks per thread per operand ----
    const float* gA[4];
    const float* gB[4];
    uint32_t soff[4];
#pragma unroll
    for (int j = 0; j < 4; j++) {
        int i = t + 256 * j;          // float4 index in 128x32 tile
        int row = i >> 3;             // 0..127
        int col = (i & 7) * 4;        // 0..28
        if (MODE == 1) {
            int r = m0 + row;
            int tok = (r < cnt) ? g_tok_of_row[e * CAP + r] : g_tok_of_row[e * CAP];
            gA[j] = g_X + (size_t)tok * KD + col;          // <-- fixed: gather from g_X
        } else {
            gA[j] = g_H + (size_t)(e * CAP + m0 + row) * KD + col;
        }
        gB[j] = Wt + ((size_t)e * ND + n0 + row) * KD + col;
        soff[j] = (uint32_t)(row * SM_PITCH + col) * 4u;
    }

    // ---- ldmatrix base addresses (bytes) ----
    const uint32_t aAddr0 = smbase +
        (uint32_t)((wm * 64 + (lane & 15)) * SM_PITCH) * 4u + (uint32_t)((lane >> 4) * 16);
    const uint32_t bAddr0 = smbase + (uint32_t)(STAGES * STAGE_BYT) +
        (uint32_t)((wn * 32 + (lane & 7)) * SM_PITCH) * 4u + (uint32_t)(((lane >> 3) & 1) * 16);

    float c[4][4][4];
#pragma unroll
    for (int am = 0; am < 4; am++)
#pragma unroll
        for (int bn = 0; bn < 4; bn++)
#pragma unroll
            for (int i = 0; i < 4; i++) c[am][bn][i] = 0.f;

    auto issue = [&](int kt, int s) {
        const int kof = kt * 32;
        const uint32_t ab = smbase + (uint32_t)(s * STAGE_BYT);
        const uint32_t bb = smbase + (uint32_t)((STAGES + s) * STAGE_BYT);
#pragma unroll
        for (int j = 0; j < 4; j++) cp16(ab + soff[j], gA[j] + kof);
#pragma unroll
        for (int j = 0; j < 4; j++) cp16(bb + soff[j], gB[j] + kof);
        asm volatile("cp.async.commit_group;");
    };

    // prologue: stages 0,1 in flight
    issue(0, 0);
    issue(1, 1);
    asm volatile("cp.async.wait_group 1;");
    __syncthreads();

    for (int kt = 0; kt < KT; kt++) {
        const int s = kt % STAGES;
        if (kt + 2 < KT) issue(kt + 2, (kt + 2) % STAGES);
        else asm volatile("cp.async.commit_group;");   // empty group keeps wait accounting

        const uint32_t aS = aAddr0 + (uint32_t)(s * STAGE_BYT);
        const uint32_t bS = bAddr0 + (uint32_t)(s * STAGE_BYT);

#pragma unroll
        for (int sl = 0; sl < 4; sl++) {
            uint32_t a[4][4], b[4][2];
#pragma unroll
            for (int am = 0; am < 4; am++)
                ldsm4(a[am], aS + am * (16 * SM_PITCH * 4) + sl * 32);
#pragma unroll
            for (int bn = 0; bn < 4; bn++)
                ldsm2(b[bn], bS + bn * (8 * SM_PITCH * 4) + sl * 32);
#pragma unroll
            for (int bn = 0; bn < 4; bn++) {   // only B needs tf32 rounding
                b[bn][0] = f2tf(__uint_as_float(b[bn][0]));
                b[bn][1] = f2tf(__uint_as_float(b[bn][1]));
            }
#pragma unroll
            for (int am = 0; am < 4; am++)
#pragma unroll
                for (int bn = 0; bn < 4; bn++)
                    mma8(c[am][bn], a[am], b[bn]);
        }

        asm volatile("cp.async.wait_group 1;");
        __syncthreads();
    }

    // ---- epilogue ----
    const int grp = lane >> 2, tig = lane & 3;
    const float* bv = bias + (size_t)e * ND + n0;
    float* Dst = (MODE == 1) ? g_H : g_Y;
#pragma unroll
    for (int bn = 0; bn < 4; bn++) {
        const int cg = wn * 32 + bn * 8 + tig * 2;
        const float b0v = bv[cg], b1v = bv[cg + 1];
#pragma unroll
        for (int am = 0; am < 4; am++) {
            const int rl = wm * 64 + am * 16 + grp;
            float v0 = c[am][bn][0] + b0v;
            float v1 = c[am][bn][1] + b1v;
            float v2 = c[am][bn][2] + b0v;
            float v3 = c[am][bn][3] + b1v;
            if (MODE == 1) {   // relu, then round so GEMM2's A needs no cvt
                v0 = rnd_tf32(fmaxf(v0, 0.f)); v1 = rnd_tf32(fmaxf(v1, 0.f));
                v2 = rnd_tf32(fmaxf(v2, 0.f)); v3 = rnd_tf32(fmaxf(v3, 0.f));
            }
            const size_t base0 = (size_t)(e * CAP + m0 + rl) * ND + n0 + cg;
            const size_t base1 = (size_t)(e * CAP + m0 + rl + 8) * ND + n0 + cg;
            *reinterpret_cast<float2*>(Dst + base0) = make_float2(v0, v1);
            *reinterpret_cast<float2*>(Dst + base1) = make_float2(v2, v3);
        }
    }
}

// ---------------- kernel 4: weighted combine ----------------
__global__ void combine_kernel(float* __restrict__ out) {
    const int n = blockIdx.x, t = threadIdx.x;
    const int r0 = g_slot_row[2 * n], r1 = g_slot_row[2 * n + 1];
    const float w0 = g_slot_w[2 * n], w1 = g_slot_w[2 * n + 1];
    const float4 a = reinterpret_cast<const float4*>(g_Y + (size_t)r0 * DOUT)[t];
    const float4 b = reinterpret_cast<const float4*>(g_Y + (size_t)r1 * DOUT)[t];
    float4 o;
    o.x = w0 * a.x + w1 * b.x;
    o.y = w0 * a.y + w1 * b.y;
    o.z = w0 * a.z + w1 * b.z;
    o.w = w0 * a.w + w1 * b.w;
    reinterpret_cast<float4*>(out + (size_t)n * DOUT)[t] = o;
}

// ---------------- launch ----------------
extern "C" void kernel_launch(void* const* d_in, const int* in_sizes, int n_in,
                              void* d_out, int out_size) {
    const float* x  = (const float*)d_in[0];
    const float* gw = (const float*)d_in[1];
    const float* gb = (const float*)d_in[2];
    const float* W1 = (const float*)d_in[3];
    const float* b1 = (const float*)d_in[4];
    const float* W2 = (const float*)d_in[5];
    const float* b2 = (const float*)d_in[6];
    float* out = (float*)d_out;

    cudaFuncSetAttribute(moe_gemm<1>, cudaFuncAttributeMaxDynamicSharedMemorySize, SMEM_BYTES);
    cudaFuncSetAttribute(moe_gemm<2>, cudaFuncAttributeMaxDynamicSharedMemorySize, SMEM_BYTES);

    init_kernel<<<1, 32>>>();
    round_x_kernel<<<NTOK * DIN / 4 / 256, 256>>>(x);
    gate_kernel<<<NTOK / 8, 256>>>(x, gw, gb);
    moe_gemm<1><<<dim3(DHID / 128, CAP / 128, NEXP), 256, SMEM_BYTES>>>(W1, b1);
    moe_gemm<2><<<dim3(DOUT / 128, CAP / 128, NEXP), 256, SMEM_BYTES>>>(W2, b2);
    combine_kernel<<<NTOK, 256>>>(out);
}